// round 8
// baseline (speedup 1.0000x reference)
#include <cuda_runtime.h>
#include <cuda_bf16.h>

#define DIM 16777216
#define TPB 256

__device__ __forceinline__ float spu_f(float z) {
    // z >= 0 : z*z - 0.5
    // z <  0 : sigmoid(-z) - 1 = -sigmoid(z) = -e^z / (1 + e^z)
    float pos = fmaf(z, z, -0.5f);
    float e = __expf(z);
    float neg = -__fdividef(e, 1.0f + e);
    return (z >= 0.0f) ? pos : neg;
}

__global__ void __launch_bounds__(TPB, 8)
spu_kernel(const float4* __restrict__ x,
           const float4* __restrict__ l,
           const float4* __restrict__ u,
           float4* __restrict__ out_x,
           float4* __restrict__ out_l,
           float4* __restrict__ out_u)
{
    int i = blockIdx.x * TPB + threadIdx.x;  // i indexes float4s; grid exactly covers DIM/4

    // L2-only loads: no reuse, skip the L1 hit path
    float4 xv = __ldcg(&x[i]);
    float4 lv = __ldcg(&l[i]);
    float4 uv = __ldcg(&u[i]);

    float4 xo, lo, uo;

    #pragma unroll
    for (int k = 0; k < 4; ++k) {
        float xs = ((const float*)&xv)[k];
        float ls = ((const float*)&lv)[k];
        float us = ((const float*)&uv)[k];

        float sx = spu_f(xs);
        float sl = spu_f(ls);
        float su = spu_f(us);

        // l_out = l>=0 ? spu(l) : (u<=0 ? spu(u) : -0.5)
        float lres = (ls >= 0.0f) ? sl : ((us <= 0.0f) ? su : -0.5f);
        // u_out = u<=0 ? spu(l) : spu(u)
        float ures = (us <= 0.0f) ? sl : su;

        ((float*)&xo)[k] = sx;
        ((float*)&lo)[k] = lres;
        ((float*)&uo)[k] = ures;
    }

    out_x[i] = xo;
    out_l[i] = lo;
    out_u[i] = uo;
}

extern "C" void kernel_launch(void* const* d_in, const int* in_sizes, int n_in,
                              void* d_out, int out_size) {
    const float4* x = (const float4*)d_in[0];
    const float4* l = (const float4*)d_in[1];
    const float4* u = (const float4*)d_in[2];

    float* out = (float*)d_out;
    float4* out_x = (float4*)(out);
    float4* out_l = (float4*)(out + DIM);
    float4* out_u = (float4*)(out + 2 * DIM);

    const int n_vec = DIM / 4;                // 4,194,304
    const int blocks = n_vec / TPB;           // 16,384
    spu_kernel<<<blocks, TPB>>>(x, l, u, out_x, out_l, out_u);
}

// round 9
// speedup vs baseline: 1.0056x; 1.0056x over previous
#include <cuda_runtime.h>
#include <cuda_bf16.h>

#define DIM 16777216
#define TPB 256

__device__ __forceinline__ float spu_f(float z) {
    // z >= 0 : z*z - 0.5
    // z <  0 : sigmoid(-z) - 1 = -sigmoid(z) = -e^z / (1 + e^z)
    float pos = fmaf(z, z, -0.5f);
    float e = __expf(z);
    float neg = -__fdividef(e, 1.0f + e);
    return (z >= 0.0f) ? pos : neg;
}

__global__ void __launch_bounds__(TPB, 8)
spu_kernel(const float4* __restrict__ x,
           const float4* __restrict__ l,
           const float4* __restrict__ u,
           float4* __restrict__ out_x,
           float4* __restrict__ out_l,
           float4* __restrict__ out_u)
{
    int i = blockIdx.x * TPB + threadIdx.x;  // i indexes float4s; grid exactly covers DIM/4

    // L2-only loads: no reuse, skip the L1 hit path
    float4 xv = __ldcg(&x[i]);
    float4 lv = __ldcg(&l[i]);
    float4 uv = __ldcg(&u[i]);

    float4 xo, lo, uo;

    #pragma unroll
    for (int k = 0; k < 4; ++k) {
        float xs = ((const float*)&xv)[k];
        float ls = ((const float*)&lv)[k];
        float us = ((const float*)&uv)[k];

        float sx = spu_f(xs);
        float sl = spu_f(ls);
        float su = spu_f(us);

        // l_out = l>=0 ? spu(l) : (u<=0 ? spu(u) : -0.5)
        float lres = (ls >= 0.0f) ? sl : ((us <= 0.0f) ? su : -0.5f);
        // u_out = u<=0 ? spu(l) : spu(u)
        float ures = (us <= 0.0f) ? sl : su;

        ((float*)&xo)[k] = sx;
        ((float*)&lo)[k] = lres;
        ((float*)&uo)[k] = ures;
    }

    out_x[i] = xo;
    out_l[i] = lo;
    out_u[i] = uo;
}

extern "C" void kernel_launch(void* const* d_in, const int* in_sizes, int n_in,
                              void* d_out, int out_size) {
    const float4* x = (const float4*)d_in[0];
    const float4* l = (const float4*)d_in[1];
    const float4* u = (const float4*)d_in[2];

    float* out = (float*)d_out;
    float4* out_x = (float4*)(out);
    float4* out_l = (float4*)(out + DIM);
    float4* out_u = (float4*)(out + 2 * DIM);

    const int n_vec = DIM / 4;                // 4,194,304
    const int blocks = n_vec / TPB;           // 16,384
    spu_kernel<<<blocks, TPB>>>(x, l, u, out_x, out_l, out_u);
}